// round 12
// baseline (speedup 1.0000x reference)
#include <cuda_runtime.h>

#define BATCH 2048
#define CELL 512
#define KDIM 30
#define LPAD 1024
#define VDIM 80

#define NCHUNK 4
#define CHUNK_B (BATCH / NCHUNK)          // 512 batches per chunk

// ---------------------------------------------------------------------------
// Kernel A: fused params + sparse phi (unchanged from round 11 except batch
// offset).  8 batches/block, 512 threads.  No register caps (r5/r8 lesson).
// ---------------------------------------------------------------------------
__global__ __launch_bounds__(512) void params_phi_kernel(
    const float* __restrict__ x,          // [B, CELL]
    const float* __restrict__ kappa_old,  // [B, K]
    const float* __restrict__ text_lens,  // [B, 1]
    const float* __restrict__ W,          // [3K, CELL]
    const float* __restrict__ bias,       // [3K]
    float* __restrict__ out_kappa,        // [B, K]
    float* __restrict__ out_phi,          // [B, L+1]
    int batch_base)
{
    __shared__ float4 xs[8][CELL / 4 + 1];
    __shared__ float s_par[8][3 * KDIM];
    __shared__ float s_phi[8][LPAD + 1];
    __shared__ float s_scale[8];
    __shared__ float s_bias[3 * KDIM];

    const int tid = threadIdx.x;
    const int wid = tid >> 5;
    const int lane = tid & 31;
    const int b0 = batch_base + blockIdx.x * 8;

    const float4* xg = (const float4*)(x + (size_t)b0 * CELL);
    for (int i = tid; i < 8 * CELL / 4; i += 512) {
        int r = i >> 7;
        int j = i & 127;
        xs[r][j] = xg[r * 128 + j];
    }
    if (tid < 3 * KDIM) s_bias[tid] = bias[tid];
    if (tid < 8) s_scale[tid] = (float)LPAD / text_lens[b0 + tid];
    for (int i = tid; i < 8 * (LPAD + 1); i += 512) {
        int r = i / (LPAD + 1);
        int l = i - r * (LPAD + 1);
        s_phi[r][l] = 0.0f;
    }
    __syncthreads();

    // ---- stage 1: 90 outputs round-robin over 16 warps, 8 batch accs ----
    for (int o = wid; o < 3 * KDIM; o += 16) {
        const float4* wrow = (const float4*)(W + (size_t)o * CELL);
        float a[8];
        #pragma unroll
        for (int r = 0; r < 8; r++) a[r] = 0.0f;

        #pragma unroll
        for (int j4 = 0; j4 < 4; j4++) {
            float4 w4 = wrow[lane + 32 * j4];
            #pragma unroll
            for (int r = 0; r < 8; r++) {
                float4 v = xs[r][lane + 32 * j4];
                a[r] = fmaf(w4.x, v.x,
                       fmaf(w4.y, v.y,
                       fmaf(w4.z, v.z,
                       fmaf(w4.w, v.w, a[r]))));
            }
        }

        // merged fold: 9 shfls; lane 4*g ends holding batch g's total
        #pragma unroll
        for (int r = 0; r < 4; r++) {
            float send = (lane & 16) ? a[r] : a[r + 4];
            float recv = __shfl_xor_sync(0xffffffffu, send, 16);
            a[r] = ((lane & 16) ? a[r + 4] : a[r]) + recv;
        }
        #pragma unroll
        for (int r = 0; r < 2; r++) {
            float send = (lane & 8) ? a[r] : a[r + 2];
            float recv = __shfl_xor_sync(0xffffffffu, send, 8);
            a[r] = ((lane & 8) ? a[r + 2] : a[r]) + recv;
        }
        {
            float send = (lane & 4) ? a[0] : a[1];
            float recv = __shfl_xor_sync(0xffffffffu, send, 4);
            a[0] = ((lane & 4) ? a[1] : a[0]) + recv;
        }
        a[0] += __shfl_xor_sync(0xffffffffu, a[0], 2);
        a[0] += __shfl_xor_sync(0xffffffffu, a[0], 1);

        if ((lane & 3) == 0) {
            int r = lane >> 2;
            int b = b0 + r;
            float p = __expf(a[0] + s_bias[o]);
            if (o >= 2 * KDIM) {
                int k = o - 2 * KDIM;
                p += kappa_old[(size_t)b * KDIM + k];
                out_kappa[(size_t)b * KDIM + k] = p;
            }
            s_par[r][o] = p;
        }
    }
    __syncthreads();

    // ---- stage 2: sparse phi (expf underflow beyond beta*d^2 > 92) ----
    for (int t = wid; t < 8 * KDIM; t += 16) {
        const int r = t / KDIM;
        const int k = t - r * KDIM;
        const float alpha = s_par[r][k];
        const float beta  = s_par[r][KDIM + k];
        const float kap   = s_par[r][2 * KDIM + k];
        const float rad = fminf(sqrtf(92.0f / beta), 1100.0f);
        const int lo = max(0, (int)(kap - rad));
        const int hi = min(LPAD, (int)(kap + rad) + 1);
        for (int l = lo + lane; l <= hi; l += 32) {
            float d = kap - (float)l;
            atomicAdd(&s_phi[r][l], alpha * __expf(-beta * d * d));
        }
    }
    __syncthreads();

    for (int i = tid; i < 8 * (LPAD + 1); i += 512) {
        int r = i / (LPAD + 1);
        int l = i - r * (LPAD + 1);
        out_phi[(size_t)(b0 + r) * (LPAD + 1) + l] = s_phi[r][l] * s_scale[r];
    }
}

// ---------------------------------------------------------------------------
// Kernel C: streaming w reduction — measured-best config, batch offset added.
// ---------------------------------------------------------------------------
__global__ __launch_bounds__(256) void wsum_kernel(
    const float4* __restrict__ onehots,   // [B, L*V/4]
    const float* __restrict__ phi,        // [B, L+1]
    float* __restrict__ out_w,            // [B, V]
    int batch_base)
{
    __shared__ float s_phi[LPAD];
    __shared__ float s_w[VDIM];

    const int bid = batch_base + blockIdx.x;
    const int tid = threadIdx.x;

    #pragma unroll
    for (int i = tid; i < LPAD; i += 256)
        s_phi[i] = phi[(size_t)bid * (LPAD + 1) + i];
    if (tid < VDIM) s_w[tid] = 0.0f;
    __syncthreads();

    const float4* oh = onehots + (size_t)bid * (LPAD * VDIM / 4);

    float4 acc[5];
    int l0[5], cb[5];
    #pragma unroll
    for (int m = 0; m < 5; m++) {
        int e0 = 4 * tid + 1024 * m;
        l0[m] = e0 / VDIM;
        cb[m] = e0 % VDIM;
        acc[m] = make_float4(0.f, 0.f, 0.f, 0.f);
    }

    #pragma unroll 2
    for (int g = 0; g < 16; g++) {
        #pragma unroll
        for (int m = 0; m < 5; m++) {
            float4 v4 = __ldcs(&oh[tid + 256 * (m + 5 * g)]);
            float ph = s_phi[l0[m] + 64 * g];
            acc[m].x = fmaf(ph, v4.x, acc[m].x);
            acc[m].y = fmaf(ph, v4.y, acc[m].y);
            acc[m].z = fmaf(ph, v4.z, acc[m].z);
            acc[m].w = fmaf(ph, v4.w, acc[m].w);
        }
    }
    __syncthreads();

    #pragma unroll
    for (int m = 0; m < 5; m++) {
        atomicAdd(&s_w[cb[m] + 0], acc[m].x);
        atomicAdd(&s_w[cb[m] + 1], acc[m].y);
        atomicAdd(&s_w[cb[m] + 2], acc[m].z);
        atomicAdd(&s_w[cb[m] + 3], acc[m].w);
    }
    __syncthreads();

    if (tid < VDIM) out_w[(size_t)bid * VDIM + tid] = s_w[tid];
}

extern "C" void kernel_launch(void* const* d_in, const int* in_sizes, int n_in,
                              void* d_out, int out_size) {
    const float* x         = (const float*)d_in[0];
    const float* kappa_old = (const float*)d_in[1];
    const float4* onehots  = (const float4*)d_in[2];
    const float* text_lens = (const float*)d_in[3];
    const float* W         = (const float*)d_in[4];
    const float* bias      = (const float*)d_in[5];

    float* out = (float*)d_out;
    float* out_w     = out;                                  // [B, V]
    float* out_kappa = out + (size_t)BATCH * VDIM;           // [B, K]
    float* out_phi   = out + (size_t)BATCH * (VDIM + KDIM);  // [B, L+1]

    // One-time infrastructure (no device memory involved; the captured work
    // graph is identical on every call).
    static cudaStream_t s2 = nullptr;
    static cudaEvent_t evP[NCHUNK];
    static cudaEvent_t evJoin;
    if (s2 == nullptr) {
        cudaStreamCreateWithFlags(&s2, cudaStreamNonBlocking);
        for (int c = 0; c < NCHUNK; c++)
            cudaEventCreateWithFlags(&evP[c], cudaEventDisableTiming);
        cudaEventCreateWithFlags(&evJoin, cudaEventDisableTiming);
    }

    // Pipeline: params+phi chunks on the origin stream; wsum chunks on s2,
    // each gated on its chunk's event (capture-legal fork); join at the end.
    for (int c = 0; c < NCHUNK; c++) {
        params_phi_kernel<<<CHUNK_B / 8, 512>>>(
            x, kappa_old, text_lens, W, bias, out_kappa, out_phi, c * CHUNK_B);
        cudaEventRecord(evP[c], 0);
        cudaStreamWaitEvent(s2, evP[c], 0);
        wsum_kernel<<<CHUNK_B, 256, 0, s2>>>(onehots, out_phi, out_w, c * CHUNK_B);
    }
    cudaEventRecord(evJoin, s2);
    cudaStreamWaitEvent(0, evJoin, 0);
}

// round 13
// speedup vs baseline: 1.1248x; 1.1248x over previous
#include <cuda_runtime.h>

#define BATCH 2048
#define CELL 512
#define KDIM 30
#define LPAD 1024
#define VDIM 80

// scratch: [B, 90] = alpha | beta | kappa (kappa pre-summed with kappa_old)
__device__ float g_params[BATCH * 3 * KDIM];

// ---------------------------------------------------------------------------
// Kernel A: params = exp(x @ W.T + b).  Register-tiled 4 outputs x 8 batches
// per warp: per j-step 12 float4 loads feed 128 lane-FMAs (1.5 B/FMA).
// 32 accumulators reduced with a 31-shfl merged fold; lane l ends holding
// pair l -> fully parallel epilogue.  8 batches/block, 512 thr, grid 256.
// ---------------------------------------------------------------------------
__global__ __launch_bounds__(512) void params_kernel(
    const float* __restrict__ x,          // [B, CELL]
    const float* __restrict__ kappa_old,  // [B, K]
    const float* __restrict__ W,          // [3K, CELL]
    const float* __restrict__ bias,       // [3K]
    float* __restrict__ out_kappa)        // [B, K]
{
    __shared__ float4 xs[8][CELL / 4 + 1];   // rows bank-shifted
    __shared__ float s_bias[3 * KDIM];

    const int tid = threadIdx.x;
    const int wid = tid >> 5;                // 16 warps
    const int lane = tid & 31;
    const int b0 = blockIdx.x * 8;

    const float4* xg = (const float4*)(x + (size_t)b0 * CELL);
    for (int i = tid; i < 8 * CELL / 4; i += 512) {
        int r = i >> 7;
        int j = i & 127;
        xs[r][j] = xg[r * 128 + j];
    }
    if (tid < 3 * KDIM) s_bias[tid] = bias[tid];
    __syncthreads();

    // 23 output-quads (outputs 4q..4q+3; q=22 covers 88..91, 90/91 guarded)
    for (int q = wid; q < 23; q += 16) {
        const int o0 = 4 * q;
        const float4* w0 = (const float4*)(W + (size_t)min(o0 + 0, 89) * CELL);
        const float4* w1 = (const float4*)(W + (size_t)min(o0 + 1, 89) * CELL);
        const float4* w2 = (const float4*)(W + (size_t)min(o0 + 2, 89) * CELL);
        const float4* w3 = (const float4*)(W + (size_t)min(o0 + 3, 89) * CELL);

        float a[32];
        #pragma unroll
        for (int i = 0; i < 32; i++) a[i] = 0.0f;

        #pragma unroll
        for (int j = 0; j < 4; j++) {
            const int idx = lane + 32 * j;
            float4 wv0 = w0[idx];
            float4 wv1 = w1[idx];
            float4 wv2 = w2[idx];
            float4 wv3 = w3[idx];
            #pragma unroll
            for (int b = 0; b < 8; b++) {
                float4 xv = xs[b][idx];
                a[0 * 8 + b] = fmaf(wv0.x, xv.x, fmaf(wv0.y, xv.y,
                               fmaf(wv0.z, xv.z, fmaf(wv0.w, xv.w, a[0 * 8 + b]))));
                a[1 * 8 + b] = fmaf(wv1.x, xv.x, fmaf(wv1.y, xv.y,
                               fmaf(wv1.z, xv.z, fmaf(wv1.w, xv.w, a[1 * 8 + b]))));
                a[2 * 8 + b] = fmaf(wv2.x, xv.x, fmaf(wv2.y, xv.y,
                               fmaf(wv2.z, xv.z, fmaf(wv2.w, xv.w, a[2 * 8 + b]))));
                a[3 * 8 + b] = fmaf(wv3.x, xv.x, fmaf(wv3.y, xv.y,
                               fmaf(wv3.z, xv.z, fmaf(wv3.w, xv.w, a[3 * 8 + b]))));
            }
        }

        // merged fold, 31 shfls: after 5 steps lane l holds pair l
        #pragma unroll
        for (int r = 0; r < 16; r++) {
            float send = (lane & 16) ? a[r] : a[r + 16];
            float recv = __shfl_xor_sync(0xffffffffu, send, 16);
            a[r] = ((lane & 16) ? a[r + 16] : a[r]) + recv;
        }
        #pragma unroll
        for (int r = 0; r < 8; r++) {
            float send = (lane & 8) ? a[r] : a[r + 8];
            float recv = __shfl_xor_sync(0xffffffffu, send, 8);
            a[r] = ((lane & 8) ? a[r + 8] : a[r]) + recv;
        }
        #pragma unroll
        for (int r = 0; r < 4; r++) {
            float send = (lane & 4) ? a[r] : a[r + 4];
            float recv = __shfl_xor_sync(0xffffffffu, send, 4);
            a[r] = ((lane & 4) ? a[r + 4] : a[r]) + recv;
        }
        #pragma unroll
        for (int r = 0; r < 2; r++) {
            float send = (lane & 2) ? a[r] : a[r + 2];
            float recv = __shfl_xor_sync(0xffffffffu, send, 2);
            a[r] = ((lane & 2) ? a[r + 2] : a[r]) + recv;
        }
        {
            float send = (lane & 1) ? a[0] : a[1];
            float recv = __shfl_xor_sync(0xffffffffu, send, 1);
            a[0] = ((lane & 1) ? a[1] : a[0]) + recv;
        }

        // lane l owns (o_sub = l>>3, b_loc = l&7)
        const int o = o0 + (lane >> 3);
        const int b = b0 + (lane & 7);
        if (o < 3 * KDIM) {
            float p = __expf(a[0] + s_bias[o]);
            if (o >= 2 * KDIM) {
                int k = o - 2 * KDIM;
                p += kappa_old[(size_t)b * KDIM + k];
                out_kappa[(size_t)b * KDIM + k] = p;
            }
            g_params[(size_t)b * (3 * KDIM) + o] = p;
        }
    }
}

// ---------------------------------------------------------------------------
// Kernel B: sparse phi.  One block per batch; Gaussian k only touched where
// beta*(kappa-l)^2 < 92 (expf underflow -> 0, matching fp32 reference).
// ---------------------------------------------------------------------------
__global__ __launch_bounds__(256) void phi_kernel(
    const float* __restrict__ text_lens,  // [B, 1]
    float* __restrict__ out_phi)          // [B, L+1]
{
    __shared__ float s_par[3 * KDIM];
    __shared__ float s_phi[LPAD + 1];

    const int bid = blockIdx.x;
    const int tid = threadIdx.x;
    const int wid = tid >> 5;
    const int lane = tid & 31;

    if (tid < 3 * KDIM)
        s_par[tid] = g_params[(size_t)bid * (3 * KDIM) + tid];
    #pragma unroll
    for (int l = tid; l <= LPAD; l += 256)
        s_phi[l] = 0.0f;
    __syncthreads();

    for (int k = wid; k < KDIM; k += 8) {
        const float alpha = s_par[k];
        const float beta  = s_par[KDIM + k];
        const float kap   = s_par[2 * KDIM + k];
        const float r = fminf(sqrtf(92.0f / beta), 1100.0f);
        const int lo = max(0, (int)(kap - r));
        const int hi = min(LPAD, (int)(kap + r) + 1);
        for (int l = lo + lane; l <= hi; l += 32) {
            float d = kap - (float)l;
            atomicAdd(&s_phi[l], alpha * __expf(-beta * d * d));
        }
    }
    __syncthreads();

    const float scale = (float)LPAD / text_lens[bid];
    for (int l = tid; l <= LPAD; l += 256)
        out_phi[(size_t)bid * (LPAD + 1) + l] = s_phi[l] * scale;
}

// ---------------------------------------------------------------------------
// Kernel C: streaming w reduction — EXACT measured-best config (grid 2048,
// block 256, ~118us @ 73% DRAM = device ceiling for this pattern). FROZEN.
// ---------------------------------------------------------------------------
__global__ __launch_bounds__(256) void wsum_kernel(
    const float4* __restrict__ onehots,   // [B, L*V/4]
    const float* __restrict__ phi,        // [B, L+1]
    float* __restrict__ out_w)            // [B, V]
{
    __shared__ float s_phi[LPAD];
    __shared__ float s_w[VDIM];

    const int bid = blockIdx.x;
    const int tid = threadIdx.x;

    #pragma unroll
    for (int i = tid; i < LPAD; i += 256)
        s_phi[i] = phi[(size_t)bid * (LPAD + 1) + i];
    if (tid < VDIM) s_w[tid] = 0.0f;
    __syncthreads();

    const float4* oh = onehots + (size_t)bid * (LPAD * VDIM / 4);

    float4 acc[5];
    int l0[5], cb[5];
    #pragma unroll
    for (int m = 0; m < 5; m++) {
        int e0 = 4 * tid + 1024 * m;
        l0[m] = e0 / VDIM;
        cb[m] = e0 % VDIM;
        acc[m] = make_float4(0.f, 0.f, 0.f, 0.f);
    }

    #pragma unroll 2
    for (int g = 0; g < 16; g++) {
        #pragma unroll
        for (int m = 0; m < 5; m++) {
            float4 v4 = __ldcs(&oh[tid + 256 * (m + 5 * g)]);
            float ph = s_phi[l0[m] + 64 * g];
            acc[m].x = fmaf(ph, v4.x, acc[m].x);
            acc[m].y = fmaf(ph, v4.y, acc[m].y);
            acc[m].z = fmaf(ph, v4.z, acc[m].z);
            acc[m].w = fmaf(ph, v4.w, acc[m].w);
        }
    }
    __syncthreads();

    #pragma unroll
    for (int m = 0; m < 5; m++) {
        atomicAdd(&s_w[cb[m] + 0], acc[m].x);
        atomicAdd(&s_w[cb[m] + 1], acc[m].y);
        atomicAdd(&s_w[cb[m] + 2], acc[m].z);
        atomicAdd(&s_w[cb[m] + 3], acc[m].w);
    }
    __syncthreads();

    if (tid < VDIM) out_w[(size_t)bid * VDIM + tid] = s_w[tid];
}

extern "C" void kernel_launch(void* const* d_in, const int* in_sizes, int n_in,
                              void* d_out, int out_size) {
    const float* x         = (const float*)d_in[0];
    const float* kappa_old = (const float*)d_in[1];
    const float4* onehots  = (const float4*)d_in[2];
    const float* text_lens = (const float*)d_in[3];
    const float* W         = (const float*)d_in[4];
    const float* bias      = (const float*)d_in[5];

    float* out = (float*)d_out;
    float* out_w     = out;                                  // [B, V]
    float* out_kappa = out + (size_t)BATCH * VDIM;           // [B, K]
    float* out_phi   = out + (size_t)BATCH * (VDIM + KDIM);  // [B, L+1]

    params_kernel<<<BATCH / 8, 512>>>(x, kappa_old, W, bias, out_kappa);
    phi_kernel<<<BATCH, 256>>>(text_lens, out_phi);
    wsum_kernel<<<BATCH, 256>>>(onehots, out_phi, out_w);
}

// round 14
// speedup vs baseline: 1.4186x; 1.2613x over previous
#include <cuda_runtime.h>

#define BATCH 2048
#define CELL 512
#define KDIM 30
#define LPAD 1024
#define VDIM 80

// scratch: [B, 90] = alpha | beta | kappa (kappa pre-summed with kappa_old)
__device__ float g_params[BATCH * 3 * KDIM];

// ---------------------------------------------------------------------------
// Kernel A: params = exp(x @ W.T + b).  r7 inner loop (8 batch accumulators,
// proven no-spill at the 128-reg budget) reshaped to 256 threads / 8 warps /
// 8 batches with launch_bounds(256,2): 2 blocks/SM, grid 256 -> ONE wave
// (r7's grid-256 @ 1 block/SM ran 1.73 waves; that tail was the slack).
// Merged 9-shfl fold (r11) + smem bias.
// ---------------------------------------------------------------------------
__global__ __launch_bounds__(256, 2) void params_kernel(
    const float* __restrict__ x,          // [B, CELL]
    const float* __restrict__ kappa_old,  // [B, K]
    const float* __restrict__ W,          // [3K, CELL]
    const float* __restrict__ bias,       // [3K]
    float* __restrict__ out_kappa)        // [B, K]
{
    __shared__ float4 xs[8][CELL / 4 + 1];   // 16.5 KB, rows bank-shifted
    __shared__ float s_bias[3 * KDIM];

    const int tid = threadIdx.x;
    const int wid = tid >> 5;                // 8 warps
    const int lane = tid & 31;
    const int b0 = blockIdx.x * 8;

    const float4* xg = (const float4*)(x + (size_t)b0 * CELL);
    for (int i = tid; i < 8 * CELL / 4; i += 256) {
        int r = i >> 7;
        int j = i & 127;
        xs[r][j] = xg[r * 128 + j];
    }
    if (tid < 3 * KDIM) s_bias[tid] = bias[tid];
    __syncthreads();

    // 90 outputs round-robin over 8 warps (11-12 each), 8 batch accs
    for (int o = wid; o < 3 * KDIM; o += 8) {
        const float4* wrow = (const float4*)(W + (size_t)o * CELL);
        float a[8];
        #pragma unroll
        for (int r = 0; r < 8; r++) a[r] = 0.0f;

        #pragma unroll
        for (int j4 = 0; j4 < 4; j4++) {
            float4 w4 = wrow[lane + 32 * j4];
            #pragma unroll
            for (int r = 0; r < 8; r++) {
                float4 v = xs[r][lane + 32 * j4];
                a[r] = fmaf(w4.x, v.x,
                       fmaf(w4.y, v.y,
                       fmaf(w4.z, v.z,
                       fmaf(w4.w, v.w, a[r]))));
            }
        }

        // merged fold: 9 shfls; lane 4*g ends holding batch g's total
        #pragma unroll
        for (int r = 0; r < 4; r++) {
            float send = (lane & 16) ? a[r] : a[r + 4];
            float recv = __shfl_xor_sync(0xffffffffu, send, 16);
            a[r] = ((lane & 16) ? a[r + 4] : a[r]) + recv;
        }
        #pragma unroll
        for (int r = 0; r < 2; r++) {
            float send = (lane & 8) ? a[r] : a[r + 2];
            float recv = __shfl_xor_sync(0xffffffffu, send, 8);
            a[r] = ((lane & 8) ? a[r + 2] : a[r]) + recv;
        }
        {
            float send = (lane & 4) ? a[0] : a[1];
            float recv = __shfl_xor_sync(0xffffffffu, send, 4);
            a[0] = ((lane & 4) ? a[1] : a[0]) + recv;
        }
        a[0] += __shfl_xor_sync(0xffffffffu, a[0], 2);
        a[0] += __shfl_xor_sync(0xffffffffu, a[0], 1);

        if ((lane & 3) == 0) {
            int r = lane >> 2;               // batch index within block
            int b = b0 + r;
            float p = __expf(a[0] + s_bias[o]);
            if (o >= 2 * KDIM) {
                int k = o - 2 * KDIM;
                p += kappa_old[(size_t)b * KDIM + k];
                out_kappa[(size_t)b * KDIM + k] = p;
            }
            g_params[(size_t)b * (3 * KDIM) + o] = p;
        }
    }
}

// ---------------------------------------------------------------------------
// Kernel B: sparse phi.  One block per batch; Gaussian k only touched where
// beta*(kappa-l)^2 < 92 (expf underflow -> 0, matching fp32 reference).
// ---------------------------------------------------------------------------
__global__ __launch_bounds__(256) void phi_kernel(
    const float* __restrict__ text_lens,  // [B, 1]
    float* __restrict__ out_phi)          // [B, L+1]
{
    __shared__ float s_par[3 * KDIM];
    __shared__ float s_phi[LPAD + 1];

    const int bid = blockIdx.x;
    const int tid = threadIdx.x;
    const int wid = tid >> 5;
    const int lane = tid & 31;

    if (tid < 3 * KDIM)
        s_par[tid] = g_params[(size_t)bid * (3 * KDIM) + tid];
    #pragma unroll
    for (int l = tid; l <= LPAD; l += 256)
        s_phi[l] = 0.0f;
    __syncthreads();

    for (int k = wid; k < KDIM; k += 8) {
        const float alpha = s_par[k];
        const float beta  = s_par[KDIM + k];
        const float kap   = s_par[2 * KDIM + k];
        const float r = fminf(sqrtf(92.0f / beta), 1100.0f);
        const int lo = max(0, (int)(kap - r));
        const int hi = min(LPAD, (int)(kap + r) + 1);
        for (int l = lo + lane; l <= hi; l += 32) {
            float d = kap - (float)l;
            atomicAdd(&s_phi[l], alpha * __expf(-beta * d * d));
        }
    }
    __syncthreads();

    const float scale = (float)LPAD / text_lens[bid];
    for (int l = tid; l <= LPAD; l += 256)
        out_phi[(size_t)bid * (LPAD + 1) + l] = s_phi[l] * scale;
}

// ---------------------------------------------------------------------------
// Kernel C: streaming w reduction — EXACT measured-best config (grid 2048,
// block 256, ~118us @ 73% DRAM = device ceiling for this pattern). FROZEN.
// ---------------------------------------------------------------------------
__global__ __launch_bounds__(256) void wsum_kernel(
    const float4* __restrict__ onehots,   // [B, L*V/4]
    const float* __restrict__ phi,        // [B, L+1]
    float* __restrict__ out_w)            // [B, V]
{
    __shared__ float s_phi[LPAD];
    __shared__ float s_w[VDIM];

    const int bid = blockIdx.x;
    const int tid = threadIdx.x;

    #pragma unroll
    for (int i = tid; i < LPAD; i += 256)
        s_phi[i] = phi[(size_t)bid * (LPAD + 1) + i];
    if (tid < VDIM) s_w[tid] = 0.0f;
    __syncthreads();

    const float4* oh = onehots + (size_t)bid * (LPAD * VDIM / 4);

    float4 acc[5];
    int l0[5], cb[5];
    #pragma unroll
    for (int m = 0; m < 5; m++) {
        int e0 = 4 * tid + 1024 * m;
        l0[m] = e0 / VDIM;
        cb[m] = e0 % VDIM;
        acc[m] = make_float4(0.f, 0.f, 0.f, 0.f);
    }

    #pragma unroll 2
    for (int g = 0; g < 16; g++) {
        #pragma unroll
        for (int m = 0; m < 5; m++) {
            float4 v4 = __ldcs(&oh[tid + 256 * (m + 5 * g)]);
            float ph = s_phi[l0[m] + 64 * g];
            acc[m].x = fmaf(ph, v4.x, acc[m].x);
            acc[m].y = fmaf(ph, v4.y, acc[m].y);
            acc[m].z = fmaf(ph, v4.z, acc[m].z);
            acc[m].w = fmaf(ph, v4.w, acc[m].w);
        }
    }
    __syncthreads();

    #pragma unroll
    for (int m = 0; m < 5; m++) {
        atomicAdd(&s_w[cb[m] + 0], acc[m].x);
        atomicAdd(&s_w[cb[m] + 1], acc[m].y);
        atomicAdd(&s_w[cb[m] + 2], acc[m].z);
        atomicAdd(&s_w[cb[m] + 3], acc[m].w);
    }
    __syncthreads();

    if (tid < VDIM) out_w[(size_t)bid * VDIM + tid] = s_w[tid];
}

extern "C" void kernel_launch(void* const* d_in, const int* in_sizes, int n_in,
                              void* d_out, int out_size) {
    const float* x         = (const float*)d_in[0];
    const float* kappa_old = (const float*)d_in[1];
    const float4* onehots  = (const float4*)d_in[2];
    const float* text_lens = (const float*)d_in[3];
    const float* W         = (const float*)d_in[4];
    const float* bias      = (const float*)d_in[5];

    float* out = (float*)d_out;
    float* out_w     = out;                                  // [B, V]
    float* out_kappa = out + (size_t)BATCH * VDIM;           // [B, K]
    float* out_phi   = out + (size_t)BATCH * (VDIM + KDIM);  // [B, L+1]

    params_kernel<<<BATCH / 8, 256>>>(x, kappa_old, W, bias, out_kappa);
    phi_kernel<<<BATCH, 256>>>(text_lens, out_phi);
    wsum_kernel<<<BATCH, 256>>>(onehots, out_phi, out_w);
}